// round 1
// baseline (speedup 1.0000x reference)
#include <cuda_runtime.h>
#include <cuda_bf16.h>
#include <cstdint>

// ---------------------------------------------------------------------------
// Fused per-pixel MLP discriminator + BCE mean.
//   x[4,19,256,512] -> 1x1 conv stack 19->64->128->256->512->1 (leaky 0.2)
//   loss = mean( max(z,0) - z*lbl + log1p(exp(-|z|)) )
// Strategy: CTA = 128 consecutive pixels. Activations bf16 in SMEM.
// Weights split hi/lo bf16 (packed interleaved) -> 2 MMAs per weight operand,
// fp32 accumulation; layer4+5 fused in epilogue (h4 never stored).
// ---------------------------------------------------------------------------

#define HW_   (256 * 512)
#define NPIX  (4 * HW_)
#define BM    128
#define LEAK  0.2f

// Packed hi/lo bf16 weights: for each row n, groups of 4 bf16:
//   [hi(k), hi(k+1), lo(k), lo(k+1)] for even k. Row stride = 2*K elems.
__device__ __nv_bfloat16 g_W1p[64 * 32 * 2];     // K padded 19->32
__device__ __nv_bfloat16 g_W2p[128 * 64 * 2];
__device__ __nv_bfloat16 g_W3p[256 * 128 * 2];
__device__ __nv_bfloat16 g_W4p[512 * 256 * 2];
__device__ double g_acc;

__global__ void prep_kernel(const float* __restrict__ W1, const float* __restrict__ W2,
                            const float* __restrict__ W3, const float* __restrict__ W4) {
    int i = blockIdx.x * blockDim.x + threadIdx.x;
    if (i == 0) g_acc = 0.0;

    if (i < 64 * 32) {                       // W1: [64][19] -> padded [64][32]
        int n = i >> 5, k = i & 31;
        float v = (k < 19) ? W1[n * 19 + k] : 0.f;
        __nv_bfloat16 hi = __float2bfloat16(v);
        __nv_bfloat16 lo = __float2bfloat16(v - __bfloat162float(hi));
        int base = (n * 32 + (k & ~1)) * 2 + (k & 1);
        g_W1p[base] = hi; g_W1p[base + 2] = lo;
    }
    if (i < 128 * 64) {                      // W2: [128][64]
        int n = i >> 6, k = i & 63;
        float v = W2[i];
        __nv_bfloat16 hi = __float2bfloat16(v);
        __nv_bfloat16 lo = __float2bfloat16(v - __bfloat162float(hi));
        int base = (n * 64 + (k & ~1)) * 2 + (k & 1);
        g_W2p[base] = hi; g_W2p[base + 2] = lo;
    }
    if (i < 256 * 128) {                     // W3: [256][128]
        int n = i >> 7, k = i & 127;
        float v = W3[i];
        __nv_bfloat16 hi = __float2bfloat16(v);
        __nv_bfloat16 lo = __float2bfloat16(v - __bfloat162float(hi));
        int base = (n * 128 + (k & ~1)) * 2 + (k & 1);
        g_W3p[base] = hi; g_W3p[base + 2] = lo;
    }
    if (i < 512 * 256) {                     // W4: [512][256]
        int n = i >> 8, k = i & 255;
        float v = W4[i];
        __nv_bfloat16 hi = __float2bfloat16(v);
        __nv_bfloat16 lo = __float2bfloat16(v - __bfloat162float(hi));
        int base = (n * 256 + (k & ~1)) * 2 + (k & 1);
        g_W4p[base] = hi; g_W4p[base + 2] = lo;
    }
}

__device__ __forceinline__ float leaky(float v) { return v >= 0.f ? v : LEAK * v; }

__device__ __forceinline__ void mma_bf16(float* c,
                                         uint32_t a0, uint32_t a1, uint32_t a2, uint32_t a3,
                                         uint32_t b0, uint32_t b1) {
    asm volatile(
        "mma.sync.aligned.m16n8k16.row.col.f32.bf16.bf16.f32 "
        "{%0,%1,%2,%3},{%4,%5,%6,%7},{%8,%9},{%0,%1,%2,%3};\n"
        : "+f"(c[0]), "+f"(c[1]), "+f"(c[2]), "+f"(c[3])
        : "r"(a0), "r"(a1), "r"(a2), "r"(a3), "r"(b0), "r"(b1));
}

// One layer GEMM: [128 x K] (SMEM bf16, row stride SS) @ W^T -> [128 x N].
// 16 warps: wm = wid>>1 owns 16 M-rows, wn = wid&1 owns N/2 columns.
// If FUSE: apply bias+leaky then dot with w5, accumulate per-pixel z (layer4+5).
template <int K, int N, int SS, int DS, bool FUSE>
__device__ __forceinline__ void do_layer(const __nv_bfloat16* sA, __nv_bfloat16* sD,
                                         const __nv_bfloat16* __restrict__ Wp,
                                         const float* __restrict__ bias,
                                         const float* __restrict__ w5, float* zacc,
                                         int wid, int lane) {
    const int wm = wid >> 1, wn = wid & 1;
    const int row0 = wm * 16;
    const int g = lane >> 2, tq = lane & 3;
    constexpr int NW = N / 2;                 // cols per warp
    constexpr int NB = (NW > 64) ? 64 : NW;   // col block (acc regs bound)
    constexpr int NBLK = NW / NB;
    constexpr int N8 = NB / 8;
    const int nwarp0 = wn * NW;

    // ldmatrix x4 lane address: rows row0+(lane&15), col halves (lane>>4)*8
    const uint32_t abase = (uint32_t)__cvta_generic_to_shared(
        sA + (row0 + (lane & 15)) * SS + ((lane >> 4) << 3));

    for (int nb = 0; nb < NBLK; ++nb) {
        float acc[N8][4];
#pragma unroll
        for (int i = 0; i < N8; ++i) { acc[i][0] = acc[i][1] = acc[i][2] = acc[i][3] = 0.f; }
        const int ncol0 = nwarp0 + nb * NB;

#pragma unroll 4
        for (int kc = 0; kc < K / 16; ++kc) {
            uint32_t a0, a1, a2, a3;
            asm volatile("ldmatrix.sync.aligned.m8n8.x4.shared.b16 {%0,%1,%2,%3},[%4];\n"
                         : "=r"(a0), "=r"(a1), "=r"(a2), "=r"(a3)
                         : "r"(abase + kc * 32));
            const int k0 = kc * 16 + tq * 2;
#pragma unroll
            for (int n8 = 0; n8 < N8; ++n8) {
                const int ncol = ncol0 + (n8 << 3) + g;
                const uint2* wp = (const uint2*)(Wp + ncol * (2 * K) + 2 * k0);
                const uint2 v0 = wp[0];   // {hi(k0,k0+1), lo(k0,k0+1)}
                const uint2 v1 = wp[4];   // {hi(k0+8,+9), lo(k0+8,+9)}  (+32B)
                mma_bf16(acc[n8], a0, a1, a2, a3, v0.x, v1.x);
                mma_bf16(acc[n8], a0, a1, a2, a3, v0.y, v1.y);
            }
        }

#pragma unroll
        for (int n8 = 0; n8 < N8; ++n8) {
            const int c0 = ncol0 + (n8 << 3) + tq * 2;
            const float bb0 = bias[c0], bb1 = bias[c0 + 1];
            const float v0 = leaky(acc[n8][0] + bb0);
            const float v1 = leaky(acc[n8][1] + bb1);
            const float v2 = leaky(acc[n8][2] + bb0);
            const float v3 = leaky(acc[n8][3] + bb1);
            if (FUSE) {
                const float w0 = w5[c0], w1 = w5[c0 + 1];
                zacc[0] += v0 * w0 + v1 * w1;   // row row0+g
                zacc[1] += v2 * w0 + v3 * w1;   // row row0+g+8
            } else {
                const int r = row0 + g;
                *(__nv_bfloat162*)(sD + r * DS + c0)       = __floats2bfloat162_rn(v0, v1);
                *(__nv_bfloat162*)(sD + (r + 8) * DS + c0) = __floats2bfloat162_rn(v2, v3);
            }
        }
    }
}

// SMEM layout (bf16 elems), all row strides padded +8 for conflict-free ldmatrix
//  xs [128][40] | h1 [128][72] | h2 [128][136] | h3 [128][264] | zs[128]f32 | red[16]f32
#define SMEM_BYTES (128 * (40 + 72 + 136 + 264) * 2 + (128 + 16) * 4)

__global__ void __launch_bounds__(512, 1)
disc_kernel(const float* __restrict__ x, const float* __restrict__ lbl,
            const float* __restrict__ b1, const float* __restrict__ b2,
            const float* __restrict__ b3, const float* __restrict__ b4,
            const float* __restrict__ W5, const float* __restrict__ b5) {
    extern __shared__ __nv_bfloat16 sm[];
    __nv_bfloat16* xs = sm;
    __nv_bfloat16* h1 = xs + 128 * 40;
    __nv_bfloat16* h2 = h1 + 128 * 72;
    __nv_bfloat16* h3 = h2 + 128 * 136;
    float* zs  = (float*)(h3 + 128 * 264);
    float* red = zs + 128;

    const int tid = threadIdx.x, wid = tid >> 5, lane = tid & 31;
    const int P0 = blockIdx.x * BM;          // 4096 CTAs x 128 pixels
    const int b  = P0 / HW_;
    const int s0 = P0 % HW_;                 // BM divides HW: no image straddle

    // Load x tile: channels strided by HW in gmem; coalesced per channel.
    for (int i = tid; i < BM * 19; i += 512) {
        const int c = i >> 7, p = i & 127;
        xs[p * 40 + c] = __float2bfloat16(x[(b * 19 + c) * HW_ + s0 + p]);
    }
    for (int i = tid; i < BM * 13; i += 512) {   // zero-pad channels 19..31
        const int c = 19 + (i >> 7), p = i & 127;
        xs[p * 40 + c] = __float2bfloat16(0.f);
    }
    if (tid < BM) zs[tid] = 0.f;
    __syncthreads();

    do_layer<32,  64,  40,  72, false>(xs, h1, g_W1p, b1, nullptr, nullptr, wid, lane);
    __syncthreads();
    do_layer<64,  128, 72,  136, false>(h1, h2, g_W2p, b2, nullptr, nullptr, wid, lane);
    __syncthreads();
    do_layer<128, 256, 136, 264, false>(h2, h3, g_W3p, b3, nullptr, nullptr, wid, lane);
    __syncthreads();

    float zacc[2] = {0.f, 0.f};
    do_layer<256, 512, 264, 2, true>(h3, nullptr, g_W4p, b4, W5, zacc, wid, lane);

    // Reduce z over the quad lanes (columns), then over the two N-half warps.
    zacc[0] += __shfl_xor_sync(0xffffffffu, zacc[0], 1);
    zacc[0] += __shfl_xor_sync(0xffffffffu, zacc[0], 2);
    zacc[1] += __shfl_xor_sync(0xffffffffu, zacc[1], 1);
    zacc[1] += __shfl_xor_sync(0xffffffffu, zacc[1], 2);
    if ((lane & 3) == 0) {
        const int r = (wid >> 1) * 16 + (lane >> 2);
        atomicAdd(&zs[r],     zacc[0]);
        atomicAdd(&zs[r + 8], zacc[1]);
    }
    __syncthreads();

    // BCE + block reduction.
    if (tid < BM) {
        const float z = zs[tid] + b5[0];
        const float l = lbl[P0 + tid];
        float bce = fmaxf(z, 0.f) - z * l + log1pf(expf(-fabsf(z)));
#pragma unroll
        for (int o = 16; o > 0; o >>= 1) bce += __shfl_xor_sync(0xffffffffu, bce, o);
        if (lane == 0) red[wid] = bce;
    }
    __syncthreads();
    if (tid == 0) atomicAdd(&g_acc, (double)(red[0] + red[1] + red[2] + red[3]));
}

__global__ void fin_kernel(float* out) {
    out[0] = (float)(g_acc * (1.0 / (double)NPIX));
}

extern "C" void kernel_launch(void* const* d_in, const int* in_sizes, int n_in,
                              void* d_out, int out_size) {
    (void)in_sizes; (void)n_in; (void)out_size;
    const float* x   = (const float*)d_in[0];
    const float* lbl = (const float*)d_in[1];
    const float* W1  = (const float*)d_in[2];
    const float* b1  = (const float*)d_in[3];
    const float* W2  = (const float*)d_in[4];
    const float* b2  = (const float*)d_in[5];
    const float* W3  = (const float*)d_in[6];
    const float* b3  = (const float*)d_in[7];
    const float* W4  = (const float*)d_in[8];
    const float* b4  = (const float*)d_in[9];
    const float* W5  = (const float*)d_in[10];
    const float* b5  = (const float*)d_in[11];

    cudaFuncSetAttribute(disc_kernel, cudaFuncAttributeMaxDynamicSharedMemorySize, SMEM_BYTES);

    prep_kernel<<<512, 256>>>(W1, W2, W3, W4);                    // weights -> hi/lo bf16, zero g_acc
    disc_kernel<<<NPIX / BM, 512, SMEM_BYTES>>>(x, lbl, b1, b2, b3, b4, W5, b5);
    fin_kernel<<<1, 1>>>((float*)d_out);
}

// round 2
// speedup vs baseline: 4.0024x; 4.0024x over previous
#include <cuda_runtime.h>
#include <cuda_fp16.h>
#include <cstdint>

// ---------------------------------------------------------------------------
// Fused per-pixel MLP discriminator + BCE mean (fp16 tensor-core version).
//   x[4,19,256,512] -> 1x1 convs 19->64->128->256->512->1 (leaky 0.2) -> BCE mean
// CTA = 128 pixels, 512 threads (16 warps = 4 M-groups x 4 N-slices).
// Weights pre-packed fp16 in MMA-fragment order, streamed GMEM->SMEM via
// cp.async in K=32 chunks (4-slot ring, prefetch depth 3). Activations fp16
// in SMEM. Layer4+5 fused in the epilogue (h4 never materialized).
// ---------------------------------------------------------------------------

#define HW_   (256 * 512)
#define NPIX  (4 * HW_)
#define BM    128
#define LEAK  0.2f

#define NCHUNKS    23          // L1:1  L2:2  L3:4  L4:16 (2 N-halves x 8 K-chunks)
#define SLOT_BYTES 16384       // max chunk = 256 cols * 32 k * 2B

// Packed fp16 weights, chunk-major. Within a chunk (N_ext cols x 32 k):
//   elem[(col*4 + tq)*8 + kc*4 + h*2 + j] = W[col][kc*16 + tq*2 + 8*h + j]
// so one LDS.128 per (col-octet thread, chunk) yields both k16-step fragments.
__device__ __align__(16) __half g_Wpk[174080];   // 2048 + 8192 + 32768 + 131072
__device__ double g_acc;

__global__ void prep_kernel(const float* __restrict__ W1, const float* __restrict__ W2,
                            const float* __restrict__ W3, const float* __restrict__ W4) {
    const int i = blockIdx.x * blockDim.x + threadIdx.x;
    if (i == 0) g_acc = 0.0;

    if (i < 64 * 32) {                    // L1: [64][19] pad K->32, chunk 0
        const int n = i >> 5, k = i & 31;
        const float v = (k < 19) ? W1[n * 19 + k] : 0.f;
        const int kc = k >> 4, r = k & 15, h = r >> 3, tq = (r & 7) >> 1, j = r & 1;
        g_Wpk[(n * 4 + tq) * 8 + kc * 4 + h * 2 + j] = __float2half_rn(v);
    }
    if (i < 128 * 64) {                   // L2: chunks 1..2
        const int n = i >> 6, k = i & 63;
        const int ch = k >> 5, kl = k & 31;
        const int kc = kl >> 4, r = kl & 15, h = r >> 3, tq = (r & 7) >> 1, j = r & 1;
        g_Wpk[2048 + ch * 4096 + (n * 4 + tq) * 8 + kc * 4 + h * 2 + j] = __float2half_rn(W2[i]);
    }
    if (i < 256 * 128) {                  // L3: chunks 3..6
        const int n = i >> 7, k = i & 127;
        const int ch = k >> 5, kl = k & 31;
        const int kc = kl >> 4, r = kl & 15, h = r >> 3, tq = (r & 7) >> 1, j = r & 1;
        g_Wpk[10240 + ch * 8192 + (n * 4 + tq) * 8 + kc * 4 + h * 2 + j] = __float2half_rn(W3[i]);
    }
    if (i < 512 * 256) {                  // L4: chunks 7..22 = [half][kchunk]
        const int n = i >> 8, k = i & 255;
        const int half = n >> 8, cl = n & 255;
        const int c8 = k >> 5, kl = k & 31;
        const int kc = kl >> 4, r = kl & 15, h = r >> 3, tq = (r & 7) >> 1, j = r & 1;
        g_Wpk[43008 + (half * 8 + c8) * 8192 + (cl * 4 + tq) * 8 + kc * 4 + h * 2 + j] =
            __float2half_rn(W4[i]);
    }
}

__device__ __forceinline__ float leaky(float v) { return v >= 0.f ? v : LEAK * v; }

__device__ __forceinline__ void mma_f16(float* c, const uint32_t* a, uint32_t b0, uint32_t b1) {
    asm volatile(
        "mma.sync.aligned.m16n8k16.row.col.f32.f16.f16.f32 "
        "{%0,%1,%2,%3},{%4,%5,%6,%7},{%8,%9},{%0,%1,%2,%3};\n"
        : "+f"(c[0]), "+f"(c[1]), "+f"(c[2]), "+f"(c[3])
        : "r"(a[0]), "r"(a[1]), "r"(a[2]), "r"(a[3]), "r"(b0), "r"(b1));
}

__device__ __forceinline__ void cp_async16(void* dst, const void* src) {
    const uint32_t d = (uint32_t)__cvta_generic_to_shared(dst);
    asm volatile("cp.async.cg.shared.global [%0], [%1], 16;\n" :: "r"(d), "l"(src) : "memory");
}
__device__ __forceinline__ void cp_commit() {
    asm volatile("cp.async.commit_group;\n" ::: "memory");
}
template <int N> __device__ __forceinline__ void cp_wait() {
    asm volatile("cp.async.wait_group %0;\n" :: "n"(N) : "memory");
}

// Issue the cp.async copies for chunk c into its ring slot; ALWAYS commits a
// group (possibly empty) so wait_group arithmetic stays uniform at the tail.
__device__ __forceinline__ void stage_chunk(int c, char* ring, int tid) {
    if (c < NCHUNKS) {
        int base_e, bytes;
        if (c == 0)      { base_e = 0;                   bytes = 4096;  }
        else if (c < 3)  { base_e = 2048  + (c - 1) * 4096; bytes = 8192;  }
        else if (c < 7)  { base_e = 10240 + (c - 3) * 8192; bytes = 16384; }
        else             { base_e = 43008 + (c - 7) * 8192; bytes = 16384; }
        char* dst = ring + (c & 3) * SLOT_BYTES;
        const char* src = (const char*)g_Wpk + base_e * 2;
        for (int off = tid * 16; off < bytes; off += 512 * 16)
            cp_async16(dst + off, src + off);
    }
    cp_commit();
}

// One GEMM pass over KP reduction dims (KP/32 streamed chunks), NW cols/warp.
// Warp owns M rows [wm*32, +32) as two m16 tiles. If FUSE: bias+leaky+w5 dot
// accumulated into zacc[4] (rows g, g+8 of each tile) instead of storing.
template <int KP, int NW, int SS, int DS, bool FUSE>
__device__ __forceinline__ void run_pass(
    const __half* sA, __half* sD, char* ring,
    const float* __restrict__ bias, const float* __restrict__ w5,
    float* zacc, int ncol0, int chunk_col0,
    int& chunk, int wm, int lane, int tid)
{
    constexpr int N8 = NW / 8;
    const int g = lane >> 2, tq = lane & 3;

    float acc[2][N8][4];
#pragma unroll
    for (int t = 0; t < 2; ++t)
#pragma unroll
        for (int n = 0; n < N8; ++n)
#pragma unroll
            for (int q = 0; q < 4; ++q) acc[t][n][q] = 0.f;

    uint32_t abase[2];
#pragma unroll
    for (int t = 0; t < 2; ++t)
        abase[t] = (uint32_t)__cvta_generic_to_shared(
            sA + (wm * 32 + t * 16 + (lane & 15)) * SS + ((lane >> 4) << 3));

    const int wbase = (ncol0 - chunk_col0) * 4 + tq;   // 16B-group index base

#pragma unroll 1
    for (int cc = 0; cc < KP / 32; ++cc) {
        cp_wait<2>();
        __syncthreads();
        const char* slot = ring + (chunk & 3) * SLOT_BYTES;

        uint32_t a[2][2][4];
#pragma unroll
        for (int t = 0; t < 2; ++t)
#pragma unroll
            for (int kc = 0; kc < 2; ++kc)
                asm volatile("ldmatrix.sync.aligned.m8n8.x4.shared.b16 {%0,%1,%2,%3},[%4];\n"
                    : "=r"(a[t][kc][0]), "=r"(a[t][kc][1]), "=r"(a[t][kc][2]), "=r"(a[t][kc][3])
                    : "r"(abase[t] + (cc * 32 + kc * 16) * 2));

#pragma unroll
        for (int n8 = 0; n8 < N8; ++n8) {
            const uint4 w = *(const uint4*)(slot + ((wbase + (n8 * 8 + g) * 4) << 4));
            mma_f16(acc[0][n8], a[0][0], w.x, w.y);
            mma_f16(acc[1][n8], a[1][0], w.x, w.y);
            mma_f16(acc[0][n8], a[0][1], w.z, w.w);
            mma_f16(acc[1][n8], a[1][1], w.z, w.w);
        }
        __syncthreads();
        stage_chunk(chunk + 3, ring, tid);
        ++chunk;
    }

#pragma unroll
    for (int t = 0; t < 2; ++t)
#pragma unroll
        for (int n8 = 0; n8 < N8; ++n8) {
            const int c0 = ncol0 + n8 * 8 + tq * 2;
            const float bb0 = bias[c0], bb1 = bias[c0 + 1];
            const float v0 = leaky(acc[t][n8][0] + bb0);
            const float v1 = leaky(acc[t][n8][1] + bb1);
            const float v2 = leaky(acc[t][n8][2] + bb0);
            const float v3 = leaky(acc[t][n8][3] + bb1);
            if (FUSE) {
                const float w50 = w5[c0], w51 = w5[c0 + 1];
                zacc[t * 2 + 0] += v0 * w50 + v1 * w51;   // row wm*32+t*16+g
                zacc[t * 2 + 1] += v2 * w50 + v3 * w51;   // row ... +8
            } else {
                const int r = wm * 32 + t * 16 + g;
                *(__half2*)(sD + r * DS + c0)       = __floats2half2_rn(v0, v1);
                *(__half2*)(sD + (r + 8) * DS + c0) = __floats2half2_rn(v2, v3);
            }
        }
}

// SMEM: activations 131072B + ring 65536B + zs/red 576B
#define SMEM_BYTES (128 * (40 + 72 + 136 + 264) * 2 + 4 * SLOT_BYTES + (128 + 16) * 4)

__global__ void __launch_bounds__(512, 1)
disc_kernel(const float* __restrict__ x, const float* __restrict__ lbl,
            const float* __restrict__ b1, const float* __restrict__ b2,
            const float* __restrict__ b3, const float* __restrict__ b4,
            const float* __restrict__ W5, const float* __restrict__ b5)
{
    extern __shared__ char smraw[];
    __half* xs = (__half*)smraw;              // [128][40]
    __half* h1 = xs + 128 * 40;               // [128][72]
    __half* h2 = h1 + 128 * 72;               // [128][136]
    __half* h3 = h2 + 128 * 136;              // [128][264]
    char*  ring = (char*)(h3 + 128 * 264);    // 4 x 16KB
    float* zs  = (float*)(ring + 4 * SLOT_BYTES);
    float* red = zs + 128;

    const int tid = threadIdx.x, wid = tid >> 5, lane = tid & 31;
    const int wm = wid >> 2, wn = wid & 3;
    const int P0 = blockIdx.x * BM;
    const int b  = P0 / HW_, s0 = P0 % HW_;   // BM | HW: no image straddle

    for (int i = tid; i < BM * 19; i += 512) {
        const int c = i >> 7, p = i & 127;
        xs[p * 40 + c] = __float2half_rn(x[(b * 19 + c) * HW_ + s0 + p]);
    }
    for (int i = tid; i < BM * 13; i += 512) {
        const int c = 19 + (i >> 7), p = i & 127;
        xs[p * 40 + c] = __float2half_rn(0.f);
    }
    if (tid < BM) zs[tid] = 0.f;

    stage_chunk(0, ring, tid);
    stage_chunk(1, ring, tid);
    stage_chunk(2, ring, tid);

    int chunk = 0;
    run_pass<32,  16, 40,  72,  false>(xs, h1, ring, b1, nullptr, nullptr, wn * 16, 0, chunk, wm, lane, tid);
    __syncthreads();
    run_pass<64,  32, 72,  136, false>(h1, h2, ring, b2, nullptr, nullptr, wn * 32, 0, chunk, wm, lane, tid);
    __syncthreads();
    run_pass<128, 64, 136, 264, false>(h2, h3, ring, b3, nullptr, nullptr, wn * 64, 0, chunk, wm, lane, tid);
    __syncthreads();

    float zacc[4] = {0.f, 0.f, 0.f, 0.f};
    run_pass<256, 64, 264, 1, true>(h3, nullptr, ring, b4, W5, zacc, wn * 64,       0,   chunk, wm, lane, tid);
    run_pass<256, 64, 264, 1, true>(h3, nullptr, ring, b4, W5, zacc, 256 + wn * 64, 256, chunk, wm, lane, tid);

#pragma unroll
    for (int q = 0; q < 4; ++q) {
        zacc[q] += __shfl_xor_sync(0xffffffffu, zacc[q], 1);
        zacc[q] += __shfl_xor_sync(0xffffffffu, zacc[q], 2);
    }
    if ((lane & 3) == 0) {
        const int g = lane >> 2;
#pragma unroll
        for (int q = 0; q < 4; ++q)
            atomicAdd(&zs[wm * 32 + (q >> 1) * 16 + (q & 1) * 8 + g], zacc[q]);
    }
    __syncthreads();

    if (tid < BM) {
        const float z = zs[tid] + b5[0];
        const float l = lbl[P0 + tid];
        float bce = fmaxf(z, 0.f) - z * l + log1pf(expf(-fabsf(z)));
#pragma unroll
        for (int o = 16; o > 0; o >>= 1) bce += __shfl_xor_sync(0xffffffffu, bce, o);
        if (lane == 0) red[wid] = bce;
    }
    __syncthreads();
    if (tid == 0) atomicAdd(&g_acc, (double)(red[0] + red[1] + red[2] + red[3]));
}

__global__ void fin_kernel(float* out) {
    out[0] = (float)(g_acc * (1.0 / (double)NPIX));
}

extern "C" void kernel_launch(void* const* d_in, const int* in_sizes, int n_in,
                              void* d_out, int out_size) {
    (void)in_sizes; (void)n_in; (void)out_size;
    const float* x   = (const float*)d_in[0];
    const float* lbl = (const float*)d_in[1];
    const float* W1  = (const float*)d_in[2];
    const float* b1  = (const float*)d_in[3];
    const float* W2  = (const float*)d_in[4];
    const float* b2  = (const float*)d_in[5];
    const float* W3  = (const float*)d_in[6];
    const float* b3  = (const float*)d_in[7];
    const float* W4  = (const float*)d_in[8];
    const float* b4  = (const float*)d_in[9];
    const float* W5  = (const float*)d_in[10];
    const float* b5  = (const float*)d_in[11];

    cudaFuncSetAttribute(disc_kernel, cudaFuncAttributeMaxDynamicSharedMemorySize, SMEM_BYTES);

    prep_kernel<<<512, 256>>>(W1, W2, W3, W4);
    disc_kernel<<<NPIX / BM, 512, SMEM_BYTES>>>(x, lbl, b1, b2, b3, b4, W5, b5);
    fin_kernel<<<1, 1>>>((float*)d_out);
}